// round 15
// baseline (speedup 1.0000x reference)
#include <cuda_runtime.h>
#include <cuda_fp16.h>
#include <stdint.h>
#include <math.h>

// ---------------- dims ----------------
#define HD 512
#define BD 512
#define TD 128

#define MB 64        // batch rows per CTA (M)
#define NU 32        // units per CTA; N = 4 gates x 32 = 128
#define KC 64        // k per stage

// smem stage layout: rows padded to 144B (64 fp16 = 128B data + 16B pad)
#define ROWB 144
#define A_BYTES (64 * ROWB)                 // 9216
#define W_BYTES (128 * ROWB)                // 18432
#define OFF_W A_BYTES
#define STAGE_BYTES (A_BYTES + W_BYTES)     // 27648
#define NSTG 4
#define OFF_XS (NSTG * STAGE_BYTES)         // 110592
// Padded past 228KB/2 = 116736 so only ONE CTA fits per SM (the R13 run
// silently packed 2 CTAs/SM onto 64 SMs, idling half the chip).
#define SMEM_TOTAL 119808

// ---------------- persistent device state ----------------
__device__ float g_c1[BD*HD];
__device__ float g_c2[BD*HD];
__device__ float g_h2f[2][BD*HD];
__device__ __align__(16) __half g_h1q[2][BD*HD];
__device__ __align__(16) __half g_h2q[2][BD*HD];
__device__ float g_b0[4*HD], g_b1[4*HD];
__device__ __align__(16) __half g_whh0[4*HD*HD];
__device__ __align__(16) __half g_wih1[4*HD*HD];
__device__ __align__(16) __half g_whh1[4*HD*HD];

// ---------------- helpers ----------------
__device__ __forceinline__ uint32_t smem_u32(const void* p) {
    uint32_t a;
    asm("{ .reg .u64 t; cvta.to.shared.u64 t, %1; cvt.u32.u64 %0, t; }" : "=r"(a) : "l"(p));
    return a;
}
__device__ __forceinline__ void cpa16(uint32_t dst, const void* src) {
    asm volatile("cp.async.cg.shared.global [%0], [%1], 16;" :: "r"(dst), "l"(src));
}
#define CP_COMMIT() asm volatile("cp.async.commit_group;")
#define CP_WAIT(n)  asm volatile("cp.async.wait_group %0;" :: "n"(n))

__device__ __forceinline__ void ldm4(uint32_t (&r)[4], uint32_t addr) {
    asm volatile("ldmatrix.sync.aligned.m8n8.x4.shared.b16 {%0,%1,%2,%3}, [%4];"
        : "=r"(r[0]), "=r"(r[1]), "=r"(r[2]), "=r"(r[3]) : "r"(addr));
}
__device__ __forceinline__ void mma_f16(float (&d)[4], const uint32_t a[4], const uint32_t b[2]) {
    asm volatile("mma.sync.aligned.m16n8k16.row.col.f32.f16.f16.f32 "
        "{%0,%1,%2,%3}, {%4,%5,%6,%7}, {%8,%9}, {%0,%1,%2,%3};"
        : "+f"(d[0]), "+f"(d[1]), "+f"(d[2]), "+f"(d[3])
        : "r"(a[0]), "r"(a[1]), "r"(a[2]), "r"(a[3]), "r"(b[0]), "r"(b[1]));
}

__device__ __forceinline__ float sigf(float z) { return 1.0f / (1.0f + __expf(-z)); }
__device__ __forceinline__ float tanhsf(float z) {
    float e = __expf(2.0f * z);
    return 1.0f - 2.0f / (e + 1.0f);
}

// ---------------- stage loader: A 64xKC fp16, W 128xKC fp16 ----------------
__device__ __forceinline__ void stage_load(uint32_t st,
    const __half* __restrict__ a, const __half* __restrict__ w,
    int b0, int u0, int k0, int tid)
{
    #pragma unroll
    for (int q = 0; q < 2; q++) {
        int i = tid + q * 256;
        int r = i >> 3, s = (i & 7) * 8;           // s in fp16 elems (16B chunks)
        uint32_t doff = (uint32_t)(r * ROWB + s * 2);
        size_t goff = (size_t)(b0 + r) * HD + k0 + s;
        cpa16(st + doff, a + goff);
    }
    #pragma unroll
    for (int q = 0; q < 4; q++) {
        int i = tid + q * 256;
        int n = i >> 3, s = (i & 7) * 8;
        int wrow = ((n >> 5) << 9) + u0 + (n & 31);  // gate*512 + u
        uint32_t doff = (uint32_t)(n * ROWB + s * 2);
        size_t goff = (size_t)wrow * HD + k0 + s;
        cpa16(st + OFF_W + doff, w + goff);
    }
}

// ---------------- compute one 64-k stage: 1 product into d ----------------
__device__ __forceinline__ void compute_stage(uint32_t sbase, float (&d)[2][4][4],
                                              int wm, int wn, int lane)
{
    const int l7 = lane & 7, grp = lane >> 3;
    const uint32_t a_row = (uint32_t)(((grp & 1) << 3) + l7);
    const uint32_t a_kb  = (uint32_t)((grp >> 1) << 4);
    const uint32_t b_n   = (uint32_t)(((grp >> 1) << 3) + l7);
    const uint32_t b_kb  = (uint32_t)((grp & 1) << 4);

    #pragma unroll
    for (int kk = 0; kk < 4; kk++) {
        uint32_t kb = kk * 32;   // bytes: k16 step = 32B
        uint32_t Ah[2][4], Bh[2][4];
        #pragma unroll
        for (int mi = 0; mi < 2; mi++) {
            uint32_t ra = sbase + (wm * 32 + mi * 16 + a_row) * ROWB + kb + a_kb;
            ldm4(Ah[mi], ra);
        }
        #pragma unroll
        for (int p = 0; p < 2; p++) {
            uint32_t rb = sbase + OFF_W + (wn * 32 + p * 16 + b_n) * ROWB + kb + b_kb;
            ldm4(Bh[p], rb);
        }
        #pragma unroll
        for (int mi = 0; mi < 2; mi++) {
            #pragma unroll
            for (int ni = 0; ni < 4; ni++) {
                const uint32_t* bh = &Bh[ni >> 1][(ni & 1) * 2];
                mma_f16(d[mi][ni], Ah[mi], bh);
            }
        }
    }
}

// ---------------- accum -> smem gate buffer ----------------
__device__ __forceinline__ void store_gbuf(float* gbuf, float (&d)[2][4][4],
                                           int wm, int wn, int lane)
{
    const int gid = lane >> 2, tig = lane & 3;
    #pragma unroll
    for (int mi = 0; mi < 2; mi++) {
        #pragma unroll
        for (int ni = 0; ni < 4; ni++) {
            int row = wm * 32 + mi * 16 + gid;
            int c0 = wn * 32 + ni * 8 + tig * 2;
            gbuf[row * 132 + c0]           = d[mi][ni][0];
            gbuf[row * 132 + c0 + 1]       = d[mi][ni][1];
            gbuf[(row + 8) * 132 + c0]     = d[mi][ni][2];
            gbuf[(row + 8) * 132 + c0 + 1] = d[mi][ni][3];
        }
    }
}

// ---------------- 4-stage ring pipeline, one sync per stage ----------------
template<int NS>
__device__ __forceinline__ void run_pipeline(
    uint32_t sb,
    const __half* const* As, const __half* const* Ws,
    int b0, int u0, int tid,
    float (&d)[2][4][4], int wm, int wn, int lane)
{
    // stages 0,1 already preloaded by caller
    #pragma unroll 1
    for (int i = 0; i < NS; i++) {
        if (i + 2 < NS) {
            int j = i + 2, sg = j >> 3;
            stage_load(sb + (j % NSTG) * STAGE_BYTES, As[sg], Ws[sg],
                       b0, u0, (j & 7) * KC, tid);
            CP_COMMIT();
            CP_WAIT(2);
        } else {
            CP_WAIT(0);
        }
        __syncthreads();
        compute_stage(sb + (i % NSTG) * STAGE_BYTES, d, wm, wn, lane);
    }
    __syncthreads();   // protect gbuf aliasing of stage slots
}

// ---------------- setup kernels ----------------
__global__ void __launch_bounds__(256) zero_state() {
    int idx = blockIdx.x * 256 + threadIdx.x;   // grid 1024
    g_c1[idx] = 0.f; g_c2[idx] = 0.f;
    __half z = __float2half(0.f);
    g_h1q[0][idx] = z; g_h2q[0][idx] = z;
}
__global__ void __launch_bounds__(256) prep_bias(
    const float* __restrict__ b_ih0, const float* __restrict__ b_hh0,
    const float* __restrict__ b_ih1, const float* __restrict__ b_hh1) {
    int j = blockIdx.x * 256 + threadIdx.x;     // grid 8
    g_b0[j] = b_ih0[j] + b_hh0[j];
    g_b1[j] = b_ih1[j] + b_hh1[j];
}
// single fp16 weight quantization
__global__ void __launch_bounds__(256) quantw1(const float* __restrict__ w, int which) {
    __half* p;
    if (which == 0)      p = g_whh0;
    else if (which == 1) p = g_wih1;
    else                 p = g_whh1;
    int i = blockIdx.x * 256 + threadIdx.x;     // grid 4096
    p[i] = __float2half_rn(w[i]);
}

// ---------------- phase A: layer-0 step ----------------
__global__ void __launch_bounds__(256) phaseA_k(
    int rd, const float* __restrict__ xin, int t, int y_from_c2,
    const float* __restrict__ w_lin, const float* __restrict__ b_lin,
    float* __restrict__ out, int t_out, const float* __restrict__ w_ih0)
{
    extern __shared__ char sm[];
    uint32_t sb = smem_u32(sm);
    const int tid = threadIdx.x, lane = tid & 31, wid = tid >> 5;
    const int wm = wid >> 2, wn = wid & 3;
    const int b0 = blockIdx.x * MB, u0 = blockIdx.y * NU;
    float* xs = (float*)(sm + OFF_XS);

    const __half* As[2] = { g_h1q[rd], g_h1q[rd] };
    const __half* Ws[2] = { g_whh0, g_whh0 };

    // kick off pipeline fill FIRST so y/x work overlaps the loads
    stage_load(sb, As[0], Ws[0], b0, u0, 0, tid);
    CP_COMMIT();
    stage_load(sb + STAGE_BYTES, As[0], Ws[0], b0, u0, KC, tid);
    CP_COMMIT();

    // input scalar per batch row (teacher-forced or autoregressive)
    if (xin != nullptr) {
        if (tid < MB) xs[tid] = xin[(size_t)(b0 + tid) * TD + t];
    } else {
        const float* ysrc = y_from_c2 ? g_c2 : g_h2f[rd];
        int rrow = tid >> 2, p = tid & 3;
        const float4* hr = (const float4*)(ysrc + (size_t)(b0 + rrow) * HD);
        const float4* wl = (const float4*)w_lin;
        float s = 0.f;
        #pragma unroll 8
        for (int kk = p; kk < HD / 4; kk += 4) {
            float4 a = hr[kk]; float4 w = wl[kk];
            s += a.x * w.x + a.y * w.y + a.z * w.z + a.w * w.w;
        }
        s += __shfl_xor_sync(0xffffffffu, s, 1);
        s += __shfl_xor_sync(0xffffffffu, s, 2);
        if (p == 0) {
            float yv = s + b_lin[0];
            xs[rrow] = yv;
            if (blockIdx.y == 0) out[(size_t)(b0 + rrow) * TD + t_out] = yv;
        }
    }

    float d[2][4][4] = {};
    run_pipeline<8>(sb, As, Ws, b0, u0, tid, d, wm, wn, lane);

    float* gbuf = (float*)sm;
    store_gbuf(gbuf, d, wm, wn, lane);
    __syncthreads();

    // cell update: thread -> (row, 8 consecutive u)
    {
        int row = tid >> 2, ub = (tid & 3) * 8;
        float xi = xs[row];
        size_t rowbase = (size_t)(b0 + row) * HD + u0 + ub;
        float4 ca = *(const float4*)(g_c1 + rowbase);
        float4 cb = *(const float4*)(g_c1 + rowbase + 4);
        float cv[8] = {ca.x, ca.y, ca.z, ca.w, cb.x, cb.y, cb.z, cb.w};
        __align__(16) __half hq[8];
        #pragma unroll
        for (int j = 0; j < 8; j++) {
            int ul = ub + j;
            int ug = u0 + ul;
            float iv = gbuf[row * 132 + ul]       + g_b0[ug]          + xi * w_ih0[ug];
            float fv = gbuf[row * 132 + 32 + ul]  + g_b0[HD + ug]     + xi * w_ih0[HD + ug];
            float gv = gbuf[row * 132 + 64 + ul]  + g_b0[2*HD + ug]   + xi * w_ih0[2*HD + ug];
            float ov = gbuf[row * 132 + 96 + ul]  + g_b0[3*HD + ug]   + xi * w_ih0[3*HD + ug];
            float cn = sigf(fv) * cv[j] + sigf(iv) * tanhsf(gv);
            cv[j] = cn;
            float h = sigf(ov) * tanhsf(cn);
            hq[j] = __float2half_rn(h);
        }
        *(float4*)(g_c1 + rowbase)     = make_float4(cv[0], cv[1], cv[2], cv[3]);
        *(float4*)(g_c1 + rowbase + 4) = make_float4(cv[4], cv[5], cv[6], cv[7]);
        *(uint4*)(g_h1q[rd ^ 1] + rowbase) = *(const uint4*)hq;
    }
}

// ---------------- phase B: layer-1 step (K=1024, two segments) ----------------
__global__ void __launch_bounds__(256) phaseB_k(int rd)
{
    extern __shared__ char sm[];
    uint32_t sb = smem_u32(sm);
    const int tid = threadIdx.x, lane = tid & 31, wid = tid >> 5;
    const int wm = wid >> 2, wn = wid & 3;
    const int b0 = blockIdx.x * MB, u0 = blockIdx.y * NU;

    const __half* As[2] = { g_h1q[rd ^ 1], g_h2q[rd] };
    const __half* Ws[2] = { g_wih1, g_whh1 };

    stage_load(sb, As[0], Ws[0], b0, u0, 0, tid);
    CP_COMMIT();
    stage_load(sb + STAGE_BYTES, As[0], Ws[0], b0, u0, KC, tid);
    CP_COMMIT();

    float d[2][4][4] = {};
    run_pipeline<16>(sb, As, Ws, b0, u0, tid, d, wm, wn, lane);

    float* gbuf = (float*)sm;
    store_gbuf(gbuf, d, wm, wn, lane);
    __syncthreads();

    {
        int row = tid >> 2, ub = (tid & 3) * 8;
        size_t rowbase = (size_t)(b0 + row) * HD + u0 + ub;
        float4 ca = *(const float4*)(g_c2 + rowbase);
        float4 cb = *(const float4*)(g_c2 + rowbase + 4);
        float cv[8] = {ca.x, ca.y, ca.z, ca.w, cb.x, cb.y, cb.z, cb.w};
        float hv[8];
        __align__(16) __half hq[8];
        #pragma unroll
        for (int j = 0; j < 8; j++) {
            int ul = ub + j;
            int ug = u0 + ul;
            float iv = gbuf[row * 132 + ul]      + g_b1[ug];
            float fv = gbuf[row * 132 + 32 + ul] + g_b1[HD + ug];
            float gv = gbuf[row * 132 + 64 + ul] + g_b1[2*HD + ug];
            float ov = gbuf[row * 132 + 96 + ul] + g_b1[3*HD + ug];
            float cn = sigf(fv) * cv[j] + sigf(iv) * tanhsf(gv);
            cv[j] = cn;
            float h = sigf(ov) * tanhsf(cn);
            hv[j] = h;
            hq[j] = __float2half_rn(h);
        }
        *(float4*)(g_c2 + rowbase)     = make_float4(cv[0], cv[1], cv[2], cv[3]);
        *(float4*)(g_c2 + rowbase + 4) = make_float4(cv[4], cv[5], cv[6], cv[7]);
        *(float4*)(g_h2f[rd ^ 1] + rowbase)     = make_float4(hv[0], hv[1], hv[2], hv[3]);
        *(float4*)(g_h2f[rd ^ 1] + rowbase + 4) = make_float4(hv[4], hv[5], hv[6], hv[7]);
        *(uint4*)(g_h2q[rd ^ 1] + rowbase) = *(const uint4*)hq;
    }
}

// ---------------- final prediction ----------------
__global__ void __launch_bounds__(256) final_y(
    int rd, const float* __restrict__ w_lin, const float* __restrict__ b_lin,
    float* __restrict__ out)
{
    int tid = threadIdx.x;
    int rrow = blockIdx.x * 128 + (tid >> 1);   // grid 4
    int p = tid & 1;
    const float4* hr = (const float4*)(g_h2f[rd] + (size_t)rrow * HD);
    const float4* wl = (const float4*)w_lin;
    float s = 0.f;
    #pragma unroll 16
    for (int kk = p; kk < HD / 4; kk += 2) {
        float4 a = hr[kk]; float4 w = wl[kk];
        s += a.x * w.x + a.y * w.y + a.z * w.z + a.w * w.w;
    }
    s += __shfl_xor_sync(0xffffffffu, s, 1);
    if (p == 0) out[(size_t)rrow * TD + (TD - 1)] = s + b_lin[0];
}

// ---------------- host launcher ----------------
extern "C" void kernel_launch(void* const* d_in, const int* in_sizes, int n_in,
                              void* d_out, int out_size)
{
    const float* x     = (const float*)d_in[0];
    const float* w_ih0 = (const float*)d_in[3];
    const float* w_hh0 = (const float*)d_in[4];
    const float* b_ih0 = (const float*)d_in[5];
    const float* b_hh0 = (const float*)d_in[6];
    const float* w_ih1 = (const float*)d_in[7];
    const float* w_hh1 = (const float*)d_in[8];
    const float* b_ih1 = (const float*)d_in[9];
    const float* b_hh1 = (const float*)d_in[10];
    const float* w_lin = (const float*)d_in[11];
    const float* b_lin = (const float*)d_in[12];
    float* out = (float*)d_out;

    cudaFuncSetAttribute(phaseA_k, cudaFuncAttributeMaxDynamicSharedMemorySize, SMEM_TOTAL);
    cudaFuncSetAttribute(phaseB_k, cudaFuncAttributeMaxDynamicSharedMemorySize, SMEM_TOTAL);

    zero_state<<<1024, 256>>>();
    prep_bias<<<8, 256>>>(b_ih0, b_hh0, b_ih1, b_hh1);
    quantw1<<<4096, 256>>>(w_hh0, 0);
    quantw1<<<4096, 256>>>(w_ih1, 1);
    quantw1<<<4096, 256>>>(w_hh1, 2);

    dim3 grid(BD / MB, HD / NU);   // (8, 16) = 128 CTAs
    int s = 0;
    for (int t = 0; t < TD; ++t, ++s) {
        phaseA_k<<<grid, 256, SMEM_TOTAL>>>(s & 1, x, t, 0,
                                            nullptr, nullptr, nullptr, 0, w_ih0);
        phaseB_k<<<grid, 256, SMEM_TOTAL>>>(s & 1);
    }
    for (int i = 1; i < TD; ++i, ++s) {
        phaseA_k<<<grid, 256, SMEM_TOTAL>>>(s & 1, nullptr, 0, (i == 1) ? 1 : 0,
                                            w_lin, b_lin, out, i - 1, w_ih0);
        phaseB_k<<<grid, 256, SMEM_TOTAL>>>(s & 1);
    }
    final_y<<<4, 256>>>(s & 1, w_lin, b_lin, out);
}

// round 16
// speedup vs baseline: 1.1669x; 1.1669x over previous
#include <cuda_runtime.h>
#include <cuda_fp16.h>
#include <stdint.h>
#include <math.h>

// ---------------- dims ----------------
#define HD 512
#define BD 512
#define TD 128

#define MB 64        // batch rows per CTA (M)
#define NU 32        // units per CTA; N = 4 gates x 32 = 128
#define KC 64        // k per stage

// smem stage layout: rows padded to 144B
#define ROWB 144
#define A_BYTES (64 * ROWB)                 // 9216
#define W_BYTES (128 * ROWB)                // 18432
#define OFF_WHI A_BYTES
#define OFF_WLO (A_BYTES + W_BYTES)
#define STAGE_BYTES (A_BYTES + 2 * W_BYTES) // 46080
#define NSTG 2
#define OFF_XS (NSTG * STAGE_BYTES)         // 92160
#define SMEM_TOTAL (OFF_XS + 1024)          // 93184  -> 2 CTAs/SM co-reside

// ---------------- persistent device state ----------------
__device__ float g_c1[BD*HD];
__device__ float g_c2[BD*HD];
__device__ float g_h2f[2][BD*HD];
__device__ __align__(16) __half g_h1q[2][BD*HD];
__device__ __align__(16) __half g_h2q[2][BD*HD];
__device__ float g_b0[4*HD], g_b1[4*HD];
__device__ __align__(16) __half g_whh0a[4*HD*HD], g_whh0b[4*HD*HD];
__device__ __align__(16) __half g_wih1a[4*HD*HD], g_wih1b[4*HD*HD];
__device__ __align__(16) __half g_whh1a[4*HD*HD], g_whh1b[4*HD*HD];

// ---------------- helpers ----------------
__device__ __forceinline__ uint32_t smem_u32(const void* p) {
    uint32_t a;
    asm("{ .reg .u64 t; cvta.to.shared.u64 t, %1; cvt.u32.u64 %0, t; }" : "=r"(a) : "l"(p));
    return a;
}
__device__ __forceinline__ void cpa16(uint32_t dst, const void* src) {
    asm volatile("cp.async.cg.shared.global [%0], [%1], 16;" :: "r"(dst), "l"(src));
}
#define CP_COMMIT() asm volatile("cp.async.commit_group;")
#define CP_WAIT(n)  asm volatile("cp.async.wait_group %0;" :: "n"(n))

__device__ __forceinline__ void ldm4(uint32_t (&r)[4], uint32_t addr) {
    asm volatile("ldmatrix.sync.aligned.m8n8.x4.shared.b16 {%0,%1,%2,%3}, [%4];"
        : "=r"(r[0]), "=r"(r[1]), "=r"(r[2]), "=r"(r[3]) : "r"(addr));
}
__device__ __forceinline__ void mma_f16(float (&d)[4], const uint32_t a[4], const uint32_t b[2]) {
    asm volatile("mma.sync.aligned.m16n8k16.row.col.f32.f16.f16.f32 "
        "{%0,%1,%2,%3}, {%4,%5,%6,%7}, {%8,%9}, {%0,%1,%2,%3};"
        : "+f"(d[0]), "+f"(d[1]), "+f"(d[2]), "+f"(d[3])
        : "r"(a[0]), "r"(a[1]), "r"(a[2]), "r"(a[3]), "r"(b[0]), "r"(b[1]));
}

__device__ __forceinline__ float rcpa(float x) {
    float r; asm("rcp.approx.f32 %0, %1;" : "=f"(r) : "f"(x)); return r;
}

// Fused LSTM cell: 5 EX2 + 2 RCP (grouped reciprocals), clamps prevent overflow.
// Updates c in place, returns h.
__device__ __forceinline__ float cellf(float iv, float fv, float gv, float ov, float& c)
{
    iv = fminf(fmaxf(iv, -25.f), 25.f);
    fv = fminf(fmaxf(fv, -25.f), 25.f);
    gv = fminf(fmaxf(gv, -12.5f), 12.5f);
    ov = fminf(fmaxf(ov, -25.f), 25.f);
    float ei = __expf(-iv), ef = __expf(-fv), eg = __expf(-2.f * gv), eo = __expf(-ov);
    float pi = 1.f + ei, pf = 1.f + ef, pg = 1.f + eg;
    float pfg = pf * pg;
    float r = rcpa(pi * pfg);
    float si = pfg * r;                 // sigmoid(i)
    float sf = (pi * pg) * r;           // sigmoid(f)
    float tg = (1.f - eg) * (pi * pf) * r;  // tanh(g)
    float cn = sf * c + si * tg;
    c = cn;
    float cc = fminf(fmaxf(cn, -12.5f), 12.5f);
    float ec = __expf(-2.f * cc);
    float r2 = rcpa((1.f + eo) * (1.f + ec));
    return (1.f - ec) * r2;             // sigmoid(o) * tanh(cn)
}

// ---------------- stage loader: A 64xKC fp16, W(hi,lo) 128xKC ----------------
__device__ __forceinline__ void stage_load(uint32_t st,
    const __half* __restrict__ a,
    const __half* __restrict__ whi, const __half* __restrict__ wlo,
    int b0, int u0, int k0, int tid)
{
    #pragma unroll
    for (int q = 0; q < 2; q++) {
        int i = tid + q * 256;
        int r = i >> 3, s = (i & 7) * 8;
        uint32_t doff = (uint32_t)(r * ROWB + s * 2);
        size_t goff = (size_t)(b0 + r) * HD + k0 + s;
        cpa16(st + doff, a + goff);
    }
    #pragma unroll
    for (int q = 0; q < 4; q++) {
        int i = tid + q * 256;
        int n = i >> 3, s = (i & 7) * 8;
        int wrow = ((n >> 5) << 9) + u0 + (n & 31);
        uint32_t doff = (uint32_t)(n * ROWB + s * 2);
        size_t goff = (size_t)wrow * HD + k0 + s;
        cpa16(st + OFF_WHI + doff, whi + goff);
        cpa16(st + OFF_WLO + doff, wlo + goff);
    }
}

// ---------------- compute one 64-k stage: 2 products ----------------
__device__ __forceinline__ void compute_stage(uint32_t sbase, float (&d)[2][4][4],
                                              int wm, int wn, int lane)
{
    const int l7 = lane & 7, grp = lane >> 3;
    const uint32_t a_row = (uint32_t)(((grp & 1) << 3) + l7);
    const uint32_t a_kb  = (uint32_t)((grp >> 1) << 4);
    const uint32_t b_n   = (uint32_t)(((grp >> 1) << 3) + l7);
    const uint32_t b_kb  = (uint32_t)((grp & 1) << 4);

    #pragma unroll
    for (int kk = 0; kk < 4; kk++) {
        uint32_t kb = kk * 32;
        uint32_t Ah[2][4], Bh[2][4], Bl[2][4];
        #pragma unroll
        for (int mi = 0; mi < 2; mi++) {
            uint32_t ra = sbase + (wm * 32 + mi * 16 + a_row) * ROWB + kb + a_kb;
            ldm4(Ah[mi], ra);
        }
        #pragma unroll
        for (int p = 0; p < 2; p++) {
            uint32_t rb = sbase + OFF_WHI + (wn * 32 + p * 16 + b_n) * ROWB + kb + b_kb;
            ldm4(Bh[p], rb);
            ldm4(Bl[p], rb + W_BYTES);
        }
        #pragma unroll
        for (int mi = 0; mi < 2; mi++) {
            #pragma unroll
            for (int ni = 0; ni < 4; ni++) {
                const uint32_t* bh = &Bh[ni >> 1][(ni & 1) * 2];
                const uint32_t* bl = &Bl[ni >> 1][(ni & 1) * 2];
                mma_f16(d[mi][ni], Ah[mi], bh);
                mma_f16(d[mi][ni], Ah[mi], bl);
            }
        }
    }
}

__device__ __forceinline__ void store_gbuf(float* gbuf, float (&d)[2][4][4],
                                           int wm, int wn, int lane)
{
    const int gid = lane >> 2, tig = lane & 3;
    #pragma unroll
    for (int mi = 0; mi < 2; mi++) {
        #pragma unroll
        for (int ni = 0; ni < 4; ni++) {
            int row = wm * 32 + mi * 16 + gid;
            int c0 = wn * 32 + ni * 8 + tig * 2;
            gbuf[row * 132 + c0]           = d[mi][ni][0];
            gbuf[row * 132 + c0 + 1]       = d[mi][ni][1];
            gbuf[(row + 8) * 132 + c0]     = d[mi][ni][2];
            gbuf[(row + 8) * 132 + c0 + 1] = d[mi][ni][3];
        }
    }
}

// ---------------- 2-stage ring, two syncs per stage (race-free) ----------------
// Caller must have issued stage_load(slot0, stage 0) + CP_COMMIT().
template<int NS>
__device__ __forceinline__ void gemm_run(uint32_t sb,
    const __half* const* As,
    const __half* const* WHs, const __half* const* WLs,
    int b0, int u0, int tid,
    float (&d)[2][4][4], int wm, int wn, int lane)
{
    #pragma unroll 1
    for (int i = 0; i < NS; i++) {
        __syncthreads();   // all warps done with compute(i-1) before overwriting its slot
        if (i + 1 < NS) {
            int sg = (i + 1) >> 3;
            stage_load(sb + ((i + 1) & 1) * STAGE_BYTES, As[sg], WHs[sg], WLs[sg],
                       b0, u0, ((i + 1) & 7) * KC, tid);
            CP_COMMIT();
            CP_WAIT(1);
        } else {
            CP_WAIT(0);
        }
        __syncthreads();
        compute_stage(sb + (i & 1) * STAGE_BYTES, d, wm, wn, lane);
    }
    __syncthreads();   // protect gbuf aliasing of stage slots
}

// ---------------- phase bodies ----------------
// layer 0 body; xs[] must be filled before first gemm sync (teacher: x, AR: y)
__device__ __forceinline__ void bodyA(char* sm, uint32_t sb, int rd,
    int b0, int u0, int tid, int lane, int wm, int wn,
    const float* __restrict__ w_ih0)
{
    float* xs = (float*)(sm + OFF_XS);
    const __half* As[2]  = { g_h1q[rd], g_h1q[rd] };
    const __half* WHs[2] = { g_whh0a, g_whh0a };
    const __half* WLs[2] = { g_whh0b, g_whh0b };

    float d[2][4][4] = {};
    gemm_run<8>(sb, As, WHs, WLs, b0, u0, tid, d, wm, wn, lane);

    float* gbuf = (float*)sm;
    store_gbuf(gbuf, d, wm, wn, lane);
    __syncthreads();

    int row = tid >> 2, ub = (tid & 3) * 8;
    float xi = xs[row];
    size_t rowbase = (size_t)(b0 + row) * HD + u0 + ub;
    float4 ca = *(const float4*)(g_c1 + rowbase);
    float4 cb = *(const float4*)(g_c1 + rowbase + 4);
    float cv[8] = {ca.x, ca.y, ca.z, ca.w, cb.x, cb.y, cb.z, cb.w};
    __align__(16) __half hq[8];
    #pragma unroll
    for (int j = 0; j < 8; j++) {
        int ul = ub + j, ug = u0 + ul;
        float iv = gbuf[row * 132 + ul]      + g_b0[ug]        + xi * w_ih0[ug];
        float fv = gbuf[row * 132 + 32 + ul] + g_b0[HD + ug]   + xi * w_ih0[HD + ug];
        float gv = gbuf[row * 132 + 64 + ul] + g_b0[2*HD + ug] + xi * w_ih0[2*HD + ug];
        float ov = gbuf[row * 132 + 96 + ul] + g_b0[3*HD + ug] + xi * w_ih0[3*HD + ug];
        hq[j] = __float2half_rn(cellf(iv, fv, gv, ov, cv[j]));
    }
    *(float4*)(g_c1 + rowbase)     = make_float4(cv[0], cv[1], cv[2], cv[3]);
    *(float4*)(g_c1 + rowbase + 4) = make_float4(cv[4], cv[5], cv[6], cv[7]);
    *(uint4*)(g_h1q[rd ^ 1] + rowbase) = *(const uint4*)hq;
}

// layer 1 body (K = 1024, two segments)
__device__ __forceinline__ void bodyB(char* sm, uint32_t sb, int rd,
    int b0, int u0, int tid, int lane, int wm, int wn)
{
    const __half* As[2]  = { g_h1q[rd ^ 1], g_h2q[rd] };
    const __half* WHs[2] = { g_wih1a, g_whh1a };
    const __half* WLs[2] = { g_wih1b, g_whh1b };

    stage_load(sb, As[0], WHs[0], WLs[0], b0, u0, 0, tid);
    CP_COMMIT();

    float d[2][4][4] = {};
    gemm_run<16>(sb, As, WHs, WLs, b0, u0, tid, d, wm, wn, lane);

    float* gbuf = (float*)sm;
    store_gbuf(gbuf, d, wm, wn, lane);
    __syncthreads();

    int row = tid >> 2, ub = (tid & 3) * 8;
    size_t rowbase = (size_t)(b0 + row) * HD + u0 + ub;
    float4 ca = *(const float4*)(g_c2 + rowbase);
    float4 cb = *(const float4*)(g_c2 + rowbase + 4);
    float cv[8] = {ca.x, ca.y, ca.z, ca.w, cb.x, cb.y, cb.z, cb.w};
    float hv[8];
    __align__(16) __half hq[8];
    #pragma unroll
    for (int j = 0; j < 8; j++) {
        int ul = ub + j, ug = u0 + ul;
        float iv = gbuf[row * 132 + ul]      + g_b1[ug];
        float fv = gbuf[row * 132 + 32 + ul] + g_b1[HD + ug];
        float gv = gbuf[row * 132 + 64 + ul] + g_b1[2*HD + ug];
        float ov = gbuf[row * 132 + 96 + ul] + g_b1[3*HD + ug];
        hv[j] = cellf(iv, fv, gv, ov, cv[j]);
        hq[j] = __float2half_rn(hv[j]);
    }
    *(float4*)(g_c2 + rowbase)     = make_float4(cv[0], cv[1], cv[2], cv[3]);
    *(float4*)(g_c2 + rowbase + 4) = make_float4(cv[4], cv[5], cv[6], cv[7]);
    *(float4*)(g_h2f[rd ^ 1] + rowbase)     = make_float4(hv[0], hv[1], hv[2], hv[3]);
    *(float4*)(g_h2f[rd ^ 1] + rowbase + 4) = make_float4(hv[4], hv[5], hv[6], hv[7]);
    *(uint4*)(g_h2q[rd ^ 1] + rowbase) = *(const uint4*)hq;
}

// ---------------- setup kernels ----------------
__global__ void __launch_bounds__(256) zero_state() {
    int idx = blockIdx.x * 256 + threadIdx.x;   // grid 1024
    g_c1[idx] = 0.f; g_c2[idx] = 0.f;
    __half z = __float2half(0.f);
    g_h1q[0][idx] = z; g_h2q[0][idx] = z;
}
__global__ void __launch_bounds__(256) prep_bias(
    const float* __restrict__ b_ih0, const float* __restrict__ b_hh0,
    const float* __restrict__ b_ih1, const float* __restrict__ b_hh1) {
    int j = blockIdx.x * 256 + threadIdx.x;     // grid 8
    g_b0[j] = b_ih0[j] + b_hh0[j];
    g_b1[j] = b_ih1[j] + b_hh1[j];
}
__global__ void __launch_bounds__(256) splitw(const float* __restrict__ w, int which) {
    __half *hi, *lo;
    if (which == 0)      { hi = g_whh0a; lo = g_whh0b; }
    else if (which == 1) { hi = g_wih1a; lo = g_wih1b; }
    else                 { hi = g_whh1a; lo = g_whh1b; }
    int i = blockIdx.x * 256 + threadIdx.x;     // grid 4096
    float v = w[i];
    __half h = __float2half_rn(v);
    hi[i] = h;
    lo[i] = __float2half_rn(v - __half2float(h));
}

// ---------------- teacher phase: fused A(t) + B(t-1) in one launch ----------------
__global__ void __launch_bounds__(256, 2) phaseAB_k(
    int t, const float* __restrict__ xin, const float* __restrict__ w_ih0)
{
    extern __shared__ char sm[];
    uint32_t sb = smem_u32(sm);
    const int tid = threadIdx.x, lane = tid & 31, wid = tid >> 5;
    const int wm = wid >> 2, wn = wid & 3;
    const int b0 = blockIdx.x * MB, u0 = blockIdx.y * NU;

    if (blockIdx.z == 0) {
        if (t >= TD) return;            // A(t) exists for t in [0, TD)
        int rd = t & 1;
        // fill pipeline stage 0 + xs
        const __half* A0 = g_h1q[rd];
        stage_load(sb, A0, g_whh0a, g_whh0b, b0, u0, 0, tid);
        CP_COMMIT();
        float* xs = (float*)(sm + OFF_XS);
        if (tid < MB) xs[tid] = xin[(size_t)(b0 + tid) * TD + t];
        bodyA(sm, sb, rd, b0, u0, tid, lane, wm, wn, w_ih0);
    } else {
        if (t == 0) return;             // B(t-1) exists for t >= 1
        int rd = (t - 1) & 1;
        bodyB(sm, sb, rd, b0, u0, tid, lane, wm, wn);
    }
}

// ---------------- AR phase A: computes y feedback, then layer-0 step ----------------
__global__ void __launch_bounds__(256, 2) phaseAR_A(
    int rd, int y_from_c2,
    const float* __restrict__ w_lin, const float* __restrict__ b_lin,
    float* __restrict__ out, int t_out, const float* __restrict__ w_ih0)
{
    extern __shared__ char sm[];
    uint32_t sb = smem_u32(sm);
    const int tid = threadIdx.x, lane = tid & 31, wid = tid >> 5;
    const int wm = wid >> 2, wn = wid & 3;
    const int b0 = blockIdx.x * MB, u0 = blockIdx.y * NU;

    // start pipeline fill first so y-compute overlaps loads
    stage_load(sb, g_h1q[rd], g_whh0a, g_whh0b, b0, u0, 0, tid);
    CP_COMMIT();

    {   // y = ysrc . w_lin + b_lin
        float* xs = (float*)(sm + OFF_XS);
        const float* ysrc = y_from_c2 ? g_c2 : g_h2f[rd];
        int rrow = tid >> 2, p = tid & 3;
        const float4* hr = (const float4*)(ysrc + (size_t)(b0 + rrow) * HD);
        const float4* wl = (const float4*)w_lin;
        float s = 0.f;
        #pragma unroll 8
        for (int kk = p; kk < HD / 4; kk += 4) {
            float4 a = hr[kk]; float4 w = wl[kk];
            s += a.x * w.x + a.y * w.y + a.z * w.z + a.w * w.w;
        }
        s += __shfl_xor_sync(0xffffffffu, s, 1);
        s += __shfl_xor_sync(0xffffffffu, s, 2);
        if (p == 0) {
            float yv = s + b_lin[0];
            xs[rrow] = yv;
            if (blockIdx.y == 0) out[(size_t)(b0 + rrow) * TD + t_out] = yv;
        }
    }

    bodyA(sm, sb, rd, b0, u0, tid, lane, wm, wn, w_ih0);
}

__global__ void __launch_bounds__(256, 2) phaseAR_B(int rd)
{
    extern __shared__ char sm[];
    uint32_t sb = smem_u32(sm);
    const int tid = threadIdx.x, lane = tid & 31, wid = tid >> 5;
    const int wm = wid >> 2, wn = wid & 3;
    const int b0 = blockIdx.x * MB, u0 = blockIdx.y * NU;
    bodyB(sm, sb, rd, b0, u0, tid, lane, wm, wn);
}

// ---------------- final prediction ----------------
__global__ void __launch_bounds__(256) final_y(
    int rd, const float* __restrict__ w_lin, const float* __restrict__ b_lin,
    float* __restrict__ out)
{
    int tid = threadIdx.x;
    int rrow = blockIdx.x * 128 + (tid >> 1);   // grid 4
    int p = tid & 1;
    const float4* hr = (const float4*)(g_h2f[rd] + (size_t)rrow * HD);
    const float4* wl = (const float4*)w_lin;
    float s = 0.f;
    #pragma unroll 16
    for (int kk = p; kk < HD / 4; kk += 2) {
        float4 a = hr[kk]; float4 w = wl[kk];
        s += a.x * w.x + a.y * w.y + a.z * w.z + a.w * w.w;
    }
    s += __shfl_xor_sync(0xffffffffu, s, 1);
    if (p == 0) out[(size_t)rrow * TD + (TD - 1)] = s + b_lin[0];
}

// ---------------- host launcher ----------------
extern "C" void kernel_launch(void* const* d_in, const int* in_sizes, int n_in,
                              void* d_out, int out_size)
{
    const float* x     = (const float*)d_in[0];
    const float* w_ih0 = (const float*)d_in[3];
    const float* w_hh0 = (const float*)d_in[4];
    const float* b_ih0 = (const float*)d_in[5];
    const float* b_hh0 = (const float*)d_in[6];
    const float* w_ih1 = (const float*)d_in[7];
    const float* w_hh1 = (const float*)d_in[8];
    const float* b_ih1 = (const float*)d_in[9];
    const float* b_hh1 = (const float*)d_in[10];
    const float* w_lin = (const float*)d_in[11];
    const float* b_lin = (const float*)d_in[12];
    float* out = (float*)d_out;

    cudaFuncSetAttribute(phaseAB_k, cudaFuncAttributeMaxDynamicSharedMemorySize, SMEM_TOTAL);
    cudaFuncSetAttribute(phaseAR_A, cudaFuncAttributeMaxDynamicSharedMemorySize, SMEM_TOTAL);
    cudaFuncSetAttribute(phaseAR_B, cudaFuncAttributeMaxDynamicSharedMemorySize, SMEM_TOTAL);

    zero_state<<<1024, 256>>>();
    prep_bias<<<8, 256>>>(b_ih0, b_hh0, b_ih1, b_hh1);
    splitw<<<4096, 256>>>(w_hh0, 0);
    splitw<<<4096, 256>>>(w_ih1, 1);
    splitw<<<4096, 256>>>(w_hh1, 2);

    // Teacher phase: launch t pairs A(t) with B(t-1) (mutually independent).
    for (int t = 0; t <= TD; ++t)
        phaseAB_k<<<dim3(8, 16, 2), 256, SMEM_TOTAL>>>(t, x, w_ih0);

    // AR phase: strict A(s) -> B(s) dependency chain.
    int s = TD;
    for (; s < 2 * TD - 1; ++s) {
        phaseAR_A<<<dim3(8, 16), 256, SMEM_TOTAL>>>(s & 1, (s == TD) ? 1 : 0,
                                                    w_lin, b_lin, out, s - TD, w_ih0);
        phaseAR_B<<<dim3(8, 16), 256, SMEM_TOTAL>>>(s & 1);
    }
    final_y<<<4, 256>>>(s & 1, w_lin, b_lin, out);
}

// round 17
// speedup vs baseline: 1.1720x; 1.0044x over previous
#include <cuda_runtime.h>
#include <cuda_fp16.h>
#include <stdint.h>
#include <math.h>

// ---------------- dims ----------------
#define HD 512
#define BD 512
#define TD 128

#define MB 64        // batch rows per CTA (M)
#define NU 32        // units per CTA; N = 4 gates x 32 = 128
#define KC 64        // k per stage

// smem stage layout: rows padded to 144B
#define ROWB 144
#define A_BYTES (64 * ROWB)                 // 9216
#define W_BYTES (128 * ROWB)                // 18432
#define OFF_WHI A_BYTES
#define OFF_WLO (A_BYTES + W_BYTES)
#define STAGE_BYTES (A_BYTES + 2 * W_BYTES) // 46080

// teacher kernel: 2-stage ring, 2 CTAs/SM co-reside
#define T_NSTG 2
#define T_OFF_XS (T_NSTG * STAGE_BYTES)     // 92160
#define T_SMEM (T_OFF_XS + 1024)            // 93184

// AR kernels: 4-stage ring, deep prefetch, 1 CTA/SM
#define R_NSTG 4
#define R_OFF_XS (R_NSTG * STAGE_BYTES)     // 184320
#define R_SMEM (R_OFF_XS + 1024)            // 185344

// ---------------- persistent device state ----------------
__device__ float g_c1[BD*HD];
__device__ float g_c2[BD*HD];
__device__ float g_h2f[2][BD*HD];
__device__ __align__(16) __half g_h1q[2][BD*HD];
__device__ __align__(16) __half g_h2q[2][BD*HD];
__device__ float g_b0[4*HD], g_b1[4*HD];
__device__ __align__(16) __half g_whh0a[4*HD*HD], g_whh0b[4*HD*HD];
__device__ __align__(16) __half g_wih1a[4*HD*HD], g_wih1b[4*HD*HD];
__device__ __align__(16) __half g_whh1a[4*HD*HD], g_whh1b[4*HD*HD];

// ---------------- helpers ----------------
__device__ __forceinline__ uint32_t smem_u32(const void* p) {
    uint32_t a;
    asm("{ .reg .u64 t; cvta.to.shared.u64 t, %1; cvt.u32.u64 %0, t; }" : "=r"(a) : "l"(p));
    return a;
}
__device__ __forceinline__ void cpa16(uint32_t dst, const void* src) {
    asm volatile("cp.async.cg.shared.global [%0], [%1], 16;" :: "r"(dst), "l"(src));
}
#define CP_COMMIT() asm volatile("cp.async.commit_group;")
#define CP_WAIT(n)  asm volatile("cp.async.wait_group %0;" :: "n"(n))

__device__ __forceinline__ void ldm4(uint32_t (&r)[4], uint32_t addr) {
    asm volatile("ldmatrix.sync.aligned.m8n8.x4.shared.b16 {%0,%1,%2,%3}, [%4];"
        : "=r"(r[0]), "=r"(r[1]), "=r"(r[2]), "=r"(r[3]) : "r"(addr));
}
__device__ __forceinline__ void mma_f16(float (&d)[4], const uint32_t a[4], const uint32_t b[2]) {
    asm volatile("mma.sync.aligned.m16n8k16.row.col.f32.f16.f16.f32 "
        "{%0,%1,%2,%3}, {%4,%5,%6,%7}, {%8,%9}, {%0,%1,%2,%3};"
        : "+f"(d[0]), "+f"(d[1]), "+f"(d[2]), "+f"(d[3])
        : "r"(a[0]), "r"(a[1]), "r"(a[2]), "r"(a[3]), "r"(b[0]), "r"(b[1]));
}

__device__ __forceinline__ float rcpa(float x) {
    float r; asm("rcp.approx.f32 %0, %1;" : "=f"(r) : "f"(x)); return r;
}

// Fused LSTM cell: 5 EX2 + 2 RCP (grouped reciprocals); clamps prevent overflow.
__device__ __forceinline__ float cellf(float iv, float fv, float gv, float ov, float& c)
{
    iv = fminf(fmaxf(iv, -25.f), 25.f);
    fv = fminf(fmaxf(fv, -25.f), 25.f);
    gv = fminf(fmaxf(gv, -12.5f), 12.5f);
    ov = fminf(fmaxf(ov, -25.f), 25.f);
    float ei = __expf(-iv), ef = __expf(-fv), eg = __expf(-2.f * gv), eo = __expf(-ov);
    float pi = 1.f + ei, pf = 1.f + ef, pg = 1.f + eg;
    float pfg = pf * pg;
    float r = rcpa(pi * pfg);
    float si = pfg * r;
    float sf = (pi * pg) * r;
    float tg = (1.f - eg) * (pi * pf) * r;
    float cn = sf * c + si * tg;
    c = cn;
    float cc = fminf(fmaxf(cn, -12.5f), 12.5f);
    float ec = __expf(-2.f * cc);
    float r2 = rcpa((1.f + eo) * (1.f + ec));
    return (1.f - ec) * r2;
}

// ---------------- stage loader ----------------
__device__ __forceinline__ void stage_load(uint32_t st,
    const __half* __restrict__ a,
    const __half* __restrict__ whi, const __half* __restrict__ wlo,
    int b0, int u0, int k0, int tid)
{
    #pragma unroll
    for (int q = 0; q < 2; q++) {
        int i = tid + q * 256;
        int r = i >> 3, s = (i & 7) * 8;
        uint32_t doff = (uint32_t)(r * ROWB + s * 2);
        size_t goff = (size_t)(b0 + r) * HD + k0 + s;
        cpa16(st + doff, a + goff);
    }
    #pragma unroll
    for (int q = 0; q < 4; q++) {
        int i = tid + q * 256;
        int n = i >> 3, s = (i & 7) * 8;
        int wrow = ((n >> 5) << 9) + u0 + (n & 31);
        uint32_t doff = (uint32_t)(n * ROWB + s * 2);
        size_t goff = (size_t)wrow * HD + k0 + s;
        cpa16(st + OFF_WHI + doff, whi + goff);
        cpa16(st + OFF_WLO + doff, wlo + goff);
    }
}

// ---------------- compute one 64-k stage: 2 products ----------------
__device__ __forceinline__ void compute_stage(uint32_t sbase, float (&d)[2][4][4],
                                              int wm, int wn, int lane)
{
    const int l7 = lane & 7, grp = lane >> 3;
    const uint32_t a_row = (uint32_t)(((grp & 1) << 3) + l7);
    const uint32_t a_kb  = (uint32_t)((grp >> 1) << 4);
    const uint32_t b_n   = (uint32_t)(((grp >> 1) << 3) + l7);
    const uint32_t b_kb  = (uint32_t)((grp & 1) << 4);

    #pragma unroll
    for (int kk = 0; kk < 4; kk++) {
        uint32_t kb = kk * 32;
        uint32_t Ah[2][4], Bh[2][4], Bl[2][4];
        #pragma unroll
        for (int mi = 0; mi < 2; mi++) {
            uint32_t ra = sbase + (wm * 32 + mi * 16 + a_row) * ROWB + kb + a_kb;
            ldm4(Ah[mi], ra);
        }
        #pragma unroll
        for (int p = 0; p < 2; p++) {
            uint32_t rb = sbase + OFF_WHI + (wn * 32 + p * 16 + b_n) * ROWB + kb + b_kb;
            ldm4(Bh[p], rb);
            ldm4(Bl[p], rb + W_BYTES);
        }
        #pragma unroll
        for (int mi = 0; mi < 2; mi++) {
            #pragma unroll
            for (int ni = 0; ni < 4; ni++) {
                const uint32_t* bh = &Bh[ni >> 1][(ni & 1) * 2];
                const uint32_t* bl = &Bl[ni >> 1][(ni & 1) * 2];
                mma_f16(d[mi][ni], Ah[mi], bh);
                mma_f16(d[mi][ni], Ah[mi], bl);
            }
        }
    }
}

__device__ __forceinline__ void store_gbuf(float* gbuf, float (&d)[2][4][4],
                                           int wm, int wn, int lane)
{
    const int gid = lane >> 2, tig = lane & 3;
    #pragma unroll
    for (int mi = 0; mi < 2; mi++) {
        #pragma unroll
        for (int ni = 0; ni < 4; ni++) {
            int row = wm * 32 + mi * 16 + gid;
            int c0 = wn * 32 + ni * 8 + tig * 2;
            gbuf[row * 132 + c0]           = d[mi][ni][0];
            gbuf[row * 132 + c0 + 1]       = d[mi][ni][1];
            gbuf[(row + 8) * 132 + c0]     = d[mi][ni][2];
            gbuf[(row + 8) * 132 + c0 + 1] = d[mi][ni][3];
        }
    }
}

// ---------------- teacher pipeline: 2-stage ring, two syncs per stage ----------------
// Caller must have issued stage_load(slot0, stage 0) + CP_COMMIT().
template<int NS>
__device__ __forceinline__ void gemm_run2(uint32_t sb,
    const __half* const* As,
    const __half* const* WHs, const __half* const* WLs,
    int b0, int u0, int tid,
    float (&d)[2][4][4], int wm, int wn, int lane)
{
    #pragma unroll 1
    for (int i = 0; i < NS; i++) {
        __syncthreads();
        if (i + 1 < NS) {
            int sg = (i + 1) >> 3;
            stage_load(sb + ((i + 1) & 1) * STAGE_BYTES, As[sg], WHs[sg], WLs[sg],
                       b0, u0, ((i + 1) & 7) * KC, tid);
            CP_COMMIT();
            CP_WAIT(1);
        } else {
            CP_WAIT(0);
        }
        __syncthreads();
        compute_stage(sb + (i & 1) * STAGE_BYTES, d, wm, wn, lane);
    }
    __syncthreads();
}

// ---------------- AR pipeline: 4-stage ring, ONE sync per stage (R12-proven) ----------
// Caller must have preloaded stages 0 and 1 (two commit groups).
template<int NS>
__device__ __forceinline__ void gemm_run4(uint32_t sb,
    const __half* const* As,
    const __half* const* WHs, const __half* const* WLs,
    int b0, int u0, int tid,
    float (&d)[2][4][4], int wm, int wn, int lane)
{
    #pragma unroll 1
    for (int i = 0; i < NS; i++) {
        if (i + 2 < NS) {
            int j = i + 2, sg = j >> 3;
            stage_load(sb + (j % R_NSTG) * STAGE_BYTES, As[sg], WHs[sg], WLs[sg],
                       b0, u0, (j & 7) * KC, tid);
            CP_COMMIT();
            CP_WAIT(2);
        } else {
            CP_WAIT(0);
        }
        __syncthreads();
        compute_stage(sb + (i % R_NSTG) * STAGE_BYTES, d, wm, wn, lane);
    }
    __syncthreads();
}

// ---------------- epilogues ----------------
__device__ __forceinline__ void epiA(char* sm, int rd, int b0, int u0, int tid,
                                     const float* __restrict__ w_ih0, const float* xs)
{
    float* gbuf = (float*)sm;
    int row = tid >> 2, ub = (tid & 3) * 8;
    float xi = xs[row];
    size_t rowbase = (size_t)(b0 + row) * HD + u0 + ub;
    float4 ca = *(const float4*)(g_c1 + rowbase);
    float4 cb = *(const float4*)(g_c1 + rowbase + 4);
    float cv[8] = {ca.x, ca.y, ca.z, ca.w, cb.x, cb.y, cb.z, cb.w};
    __align__(16) __half hq[8];
    #pragma unroll
    for (int j = 0; j < 8; j++) {
        int ul = ub + j, ug = u0 + ul;
        float iv = gbuf[row * 132 + ul]      + g_b0[ug]        + xi * w_ih0[ug];
        float fv = gbuf[row * 132 + 32 + ul] + g_b0[HD + ug]   + xi * w_ih0[HD + ug];
        float gv = gbuf[row * 132 + 64 + ul] + g_b0[2*HD + ug] + xi * w_ih0[2*HD + ug];
        float ov = gbuf[row * 132 + 96 + ul] + g_b0[3*HD + ug] + xi * w_ih0[3*HD + ug];
        hq[j] = __float2half_rn(cellf(iv, fv, gv, ov, cv[j]));
    }
    *(float4*)(g_c1 + rowbase)     = make_float4(cv[0], cv[1], cv[2], cv[3]);
    *(float4*)(g_c1 + rowbase + 4) = make_float4(cv[4], cv[5], cv[6], cv[7]);
    *(uint4*)(g_h1q[rd ^ 1] + rowbase) = *(const uint4*)hq;
}

__device__ __forceinline__ void epiB(char* sm, int rd, int b0, int u0, int tid)
{
    float* gbuf = (float*)sm;
    int row = tid >> 2, ub = (tid & 3) * 8;
    size_t rowbase = (size_t)(b0 + row) * HD + u0 + ub;
    float4 ca = *(const float4*)(g_c2 + rowbase);
    float4 cb = *(const float4*)(g_c2 + rowbase + 4);
    float cv[8] = {ca.x, ca.y, ca.z, ca.w, cb.x, cb.y, cb.z, cb.w};
    float hv[8];
    __align__(16) __half hq[8];
    #pragma unroll
    for (int j = 0; j < 8; j++) {
        int ul = ub + j, ug = u0 + ul;
        float iv = gbuf[row * 132 + ul]      + g_b1[ug];
        float fv = gbuf[row * 132 + 32 + ul] + g_b1[HD + ug];
        float gv = gbuf[row * 132 + 64 + ul] + g_b1[2*HD + ug];
        float ov = gbuf[row * 132 + 96 + ul] + g_b1[3*HD + ug];
        hv[j] = cellf(iv, fv, gv, ov, cv[j]);
        hq[j] = __float2half_rn(hv[j]);
    }
    *(float4*)(g_c2 + rowbase)     = make_float4(cv[0], cv[1], cv[2], cv[3]);
    *(float4*)(g_c2 + rowbase + 4) = make_float4(cv[4], cv[5], cv[6], cv[7]);
    *(float4*)(g_h2f[rd ^ 1] + rowbase)     = make_float4(hv[0], hv[1], hv[2], hv[3]);
    *(float4*)(g_h2f[rd ^ 1] + rowbase + 4) = make_float4(hv[4], hv[5], hv[6], hv[7]);
    *(uint4*)(g_h2q[rd ^ 1] + rowbase) = *(const uint4*)hq;
}

// ---------------- setup kernels ----------------
__global__ void __launch_bounds__(256) zero_state() {
    int idx = blockIdx.x * 256 + threadIdx.x;   // grid 1024
    g_c1[idx] = 0.f; g_c2[idx] = 0.f;
    __half z = __float2half(0.f);
    g_h1q[0][idx] = z; g_h2q[0][idx] = z;
}
__global__ void __launch_bounds__(256) prep_bias(
    const float* __restrict__ b_ih0, const float* __restrict__ b_hh0,
    const float* __restrict__ b_ih1, const float* __restrict__ b_hh1) {
    int j = blockIdx.x * 256 + threadIdx.x;     // grid 8
    g_b0[j] = b_ih0[j] + b_hh0[j];
    g_b1[j] = b_ih1[j] + b_hh1[j];
}
__global__ void __launch_bounds__(256) splitw(const float* __restrict__ w, int which) {
    __half *hi, *lo;
    if (which == 0)      { hi = g_whh0a; lo = g_whh0b; }
    else if (which == 1) { hi = g_wih1a; lo = g_wih1b; }
    else                 { hi = g_whh1a; lo = g_whh1b; }
    int i = blockIdx.x * 256 + threadIdx.x;     // grid 4096
    float v = w[i];
    __half h = __float2half_rn(v);
    hi[i] = h;
    lo[i] = __float2half_rn(v - __half2float(h));
}

// ---------------- teacher phase: fused A(t) + B(t-1), 2-stage ring ----------------
__global__ void __launch_bounds__(256, 2) phaseAB_k(
    int t, const float* __restrict__ xin, const float* __restrict__ w_ih0)
{
    extern __shared__ char sm[];
    uint32_t sb = smem_u32(sm);
    const int tid = threadIdx.x, lane = tid & 31, wid = tid >> 5;
    const int wm = wid >> 2, wn = wid & 3;
    const int b0 = blockIdx.x * MB, u0 = blockIdx.y * NU;

    if (blockIdx.z == 0) {
        if (t >= TD) return;
        int rd = t & 1;
        const __half* As[2]  = { g_h1q[rd], g_h1q[rd] };
        const __half* WHs[2] = { g_whh0a, g_whh0a };
        const __half* WLs[2] = { g_whh0b, g_whh0b };
        stage_load(sb, As[0], WHs[0], WLs[0], b0, u0, 0, tid);
        CP_COMMIT();
        float* xs = (float*)(sm + T_OFF_XS);
        if (tid < MB) xs[tid] = xin[(size_t)(b0 + tid) * TD + t];
        float d[2][4][4] = {};
        gemm_run2<8>(sb, As, WHs, WLs, b0, u0, tid, d, wm, wn, lane);
        store_gbuf((float*)sm, d, wm, wn, lane);
        __syncthreads();
        epiA(sm, rd, b0, u0, tid, w_ih0, xs);
    } else {
        if (t == 0) return;
        int rd = (t - 1) & 1;
        const __half* As[2]  = { g_h1q[rd ^ 1], g_h2q[rd] };
        const __half* WHs[2] = { g_wih1a, g_whh1a };
        const __half* WLs[2] = { g_wih1b, g_whh1b };
        stage_load(sb, As[0], WHs[0], WLs[0], b0, u0, 0, tid);
        CP_COMMIT();
        float d[2][4][4] = {};
        gemm_run2<16>(sb, As, WHs, WLs, b0, u0, tid, d, wm, wn, lane);
        store_gbuf((float*)sm, d, wm, wn, lane);
        __syncthreads();
        epiB(sm, rd, b0, u0, tid);
    }
}

// ---------------- AR phase A: 4-stage ring ----------------
__global__ void __launch_bounds__(256) phaseAR_A(
    int rd, int y_from_c2,
    const float* __restrict__ w_lin, const float* __restrict__ b_lin,
    float* __restrict__ out, int t_out, const float* __restrict__ w_ih0)
{
    extern __shared__ char sm[];
    uint32_t sb = smem_u32(sm);
    const int tid = threadIdx.x, lane = tid & 31, wid = tid >> 5;
    const int wm = wid >> 2, wn = wid & 3;
    const int b0 = blockIdx.x * MB, u0 = blockIdx.y * NU;
    float* xs = (float*)(sm + R_OFF_XS);

    const __half* As[2]  = { g_h1q[rd], g_h1q[rd] };
    const __half* WHs[2] = { g_whh0a, g_whh0a };
    const __half* WLs[2] = { g_whh0b, g_whh0b };

    // fill stages 0,1 first so y-compute overlaps the loads
    stage_load(sb, As[0], WHs[0], WLs[0], b0, u0, 0, tid);
    CP_COMMIT();
    stage_load(sb + STAGE_BYTES, As[0], WHs[0], WLs[0], b0, u0, KC, tid);
    CP_COMMIT();

    {   // y = ysrc . w_lin + b_lin
        const float* ysrc = y_from_c2 ? g_c2 : g_h2f[rd];
        int rrow = tid >> 2, p = tid & 3;
        const float4* hr = (const float4*)(ysrc + (size_t)(b0 + rrow) * HD);
        const float4* wl = (const float4*)w_lin;
        float s = 0.f;
        #pragma unroll 8
        for (int kk = p; kk < HD / 4; kk += 4) {
            float4 a = hr[kk]; float4 w = wl[kk];
            s += a.x * w.x + a.y * w.y + a.z * w.z + a.w * w.w;
        }
        s += __shfl_xor_sync(0xffffffffu, s, 1);
        s += __shfl_xor_sync(0xffffffffu, s, 2);
        if (p == 0) {
            float yv = s + b_lin[0];
            xs[rrow] = yv;
            if (blockIdx.y == 0) out[(size_t)(b0 + rrow) * TD + t_out] = yv;
        }
    }

    float d[2][4][4] = {};
    gemm_run4<8>(sb, As, WHs, WLs, b0, u0, tid, d, wm, wn, lane);
    store_gbuf((float*)sm, d, wm, wn, lane);
    __syncthreads();
    epiA(sm, rd, b0, u0, tid, w_ih0, xs);
}

// ---------------- AR phase B: 4-stage ring ----------------
__global__ void __launch_bounds__(256) phaseAR_B(int rd)
{
    extern __shared__ char sm[];
    uint32_t sb = smem_u32(sm);
    const int tid = threadIdx.x, lane = tid & 31, wid = tid >> 5;
    const int wm = wid >> 2, wn = wid & 3;
    const int b0 = blockIdx.x * MB, u0 = blockIdx.y * NU;

    const __half* As[2]  = { g_h1q[rd ^ 1], g_h2q[rd] };
    const __half* WHs[2] = { g_wih1a, g_whh1a };
    const __half* WLs[2] = { g_wih1b, g_whh1b };

    stage_load(sb, As[0], WHs[0], WLs[0], b0, u0, 0, tid);
    CP_COMMIT();
    stage_load(sb + STAGE_BYTES, As[0], WHs[0], WLs[0], b0, u0, KC, tid);
    CP_COMMIT();

    float d[2][4][4] = {};
    gemm_run4<16>(sb, As, WHs, WLs, b0, u0, tid, d, wm, wn, lane);
    store_gbuf((float*)sm, d, wm, wn, lane);
    __syncthreads();
    epiB(sm, rd, b0, u0, tid);
}

// ---------------- final prediction ----------------
__global__ void __launch_bounds__(256) final_y(
    int rd, const float* __restrict__ w_lin, const float* __restrict__ b_lin,
    float* __restrict__ out)
{
    int tid = threadIdx.x;
    int rrow = blockIdx.x * 128 + (tid >> 1);   // grid 4
    int p = tid & 1;
    const float4* hr = (const float4*)(g_h2f[rd] + (size_t)rrow * HD);
    const float4* wl = (const float4*)w_lin;
    float s = 0.f;
    #pragma unroll 16
    for (int kk = p; kk < HD / 4; kk += 2) {
        float4 a = hr[kk]; float4 w = wl[kk];
        s += a.x * w.x + a.y * w.y + a.z * w.z + a.w * w.w;
    }
    s += __shfl_xor_sync(0xffffffffu, s, 1);
    if (p == 0) out[(size_t)rrow * TD + (TD - 1)] = s + b_lin[0];
}

// ---------------- host launcher ----------------
extern "C" void kernel_launch(void* const* d_in, const int* in_sizes, int n_in,
                              void* d_out, int out_size)
{
    const float* x     = (const float*)d_in[0];
    const float* w_ih0 = (const float*)d_in[3];
    const float* w_hh0 = (const float*)d_in[4];
    const float* b_ih0 = (const float*)d_in[5];
    const float* b_hh0 = (const float*)d_in[6];
    const float* w_ih1 = (const float*)d_in[7];
    const float* w_hh1 = (const float*)d_in[8];
    const float* b_ih1 = (const float*)d_in[9];
    const float* b_hh1 = (const float*)d_in[10];
    const float* w_lin = (const float*)d_in[11];
    const float* b_lin = (const float*)d_in[12];
    float* out = (float*)d_out;

    cudaFuncSetAttribute(phaseAB_k, cudaFuncAttributeMaxDynamicSharedMemorySize, T_SMEM);
    cudaFuncSetAttribute(phaseAR_A, cudaFuncAttributeMaxDynamicSharedMemorySize, R_SMEM);
    cudaFuncSetAttribute(phaseAR_B, cudaFuncAttributeMaxDynamicSharedMemorySize, R_SMEM);

    zero_state<<<1024, 256>>>();
    prep_bias<<<8, 256>>>(b_ih0, b_hh0, b_ih1, b_hh1);
    splitw<<<4096, 256>>>(w_hh0, 0);
    splitw<<<4096, 256>>>(w_ih1, 1);
    splitw<<<4096, 256>>>(w_hh1, 2);

    // Teacher phase: A(t) fused with B(t-1) (mutually independent).
    for (int t = 0; t <= TD; ++t)
        phaseAB_k<<<dim3(8, 16, 2), 256, T_SMEM>>>(t, x, w_ih0);

    // AR phase: strict A(s) -> B(s) chain, deep-pipelined kernels.
    int s = TD;
    for (; s < 2 * TD - 1; ++s) {
        phaseAR_A<<<dim3(8, 16), 256, R_SMEM>>>(s & 1, (s == TD) ? 1 : 0,
                                                w_lin, b_lin, out, s - TD, w_ih0);
        phaseAR_B<<<dim3(8, 16), 256, R_SMEM>>>(s & 1);
    }
    final_y<<<4, 256>>>(s & 1, w_lin, b_lin, out);
}